// round 11
// baseline (speedup 1.0000x reference)
#include <cuda_runtime.h>
#include <cuda_bf16.h>
#include <cstdint>
#include <math.h>

#define BATCH_ 4096
#define HID_   2048
#define KTOT   4096            // K = INPUT(2048 from x) ++ HIDDEN(2048 from h)
#define BH     ((size_t)BATCH_ * HID_)

// GEMM tiling: CTA = 128(m) x 64(n) x 4 gates  (256 B-rows staged)
#define BM 128
#define BN 64
#define BK 32
#define STAGES 4
#define NKC (KTOT / BK)        // 128 k-iterations

// SMEM stage layout (48KB per stage, 4 stages = 192KB)
#define OFF_AHI 0
#define OFF_ALO 8192
#define OFF_BHI 16384
#define OFF_BLO 32768
#define ST_BYTES 49152
#define SMEM_TOTAL (STAGES * ST_BYTES)

// Epilogue exchange layout (reuses the same dynamic smem after the mainloop)
#define EPS_STRIDE 265                   // floats per m-row (9 mod 32 -> conflict-free)
#define BIAS_OFF   (128 * EPS_STRIDE)    // 256 bias floats after the tile

// ---------------- scratch (device globals; allocation-free) ----------------
__device__ __nv_bfloat16 g_A_hi[(size_t)BATCH_ * KTOT];      // [b][k]        32MB
__device__ __nv_bfloat16 g_A_lo[(size_t)BATCH_ * KTOT];
__device__ __nv_bfloat16 g_B_hi[(size_t)4 * HID_ * KTOT];    // [g*2048+n][k] 64MB
__device__ __nv_bfloat16 g_B_lo[(size_t)4 * HID_ * KTOT];

// ---------------- PTX helpers (base ISA only) ----------------
__device__ __forceinline__ uint32_t smem_u32(const void* p) {
    uint32_t a;
    asm("{ .reg .u64 t; cvta.to.shared.u64 t, %1; cvt.u32.u64 %0, t; }" : "=r"(a) : "l"(p));
    return a;
}
__device__ __forceinline__ void cp16(uint32_t dst, const void* src) {
    asm volatile("cp.async.cg.shared.global [%0], [%1], 16;" :: "r"(dst), "l"(src));
}
__device__ __forceinline__ void cp_commit() { asm volatile("cp.async.commit_group;" ::: "memory"); }
template <int N>
__device__ __forceinline__ void cp_wait() { asm volatile("cp.async.wait_group %0;" :: "n"(N) : "memory"); }

__device__ __forceinline__ void ldsm4(uint32_t* r, uint32_t addr) {
    asm volatile("ldmatrix.sync.aligned.m8n8.x4.shared.b16 {%0,%1,%2,%3}, [%4];"
                 : "=r"(r[0]), "=r"(r[1]), "=r"(r[2]), "=r"(r[3]) : "r"(addr));
}
__device__ __forceinline__ void mma16816(float* d, const uint32_t* a, uint32_t b0, uint32_t b1) {
    asm volatile(
        "mma.sync.aligned.m16n8k16.row.col.f32.bf16.bf16.f32 "
        "{%0,%1,%2,%3}, {%4,%5,%6,%7}, {%8,%9}, {%0,%1,%2,%3};"
        : "+f"(d[0]), "+f"(d[1]), "+f"(d[2]), "+f"(d[3])
        : "r"(a[0]), "r"(a[1]), "r"(a[2]), "r"(a[3]), "r"(b0), "r"(b1));
}

// 64B-row swizzle: 16B-column index XORed with (row>>1)&3 -> conflict-free for
// cp.async 16B stores and ldmatrix 8-row groups.  (proven in R10)
__device__ __forceinline__ uint32_t sw64(int row, int k2) {
    return (uint32_t)(row * 64 + ((k2 ^ ((row >> 1) & 3)) << 4));
}

// ---------------- conversion kernels (unchanged from R10) ----------------
__device__ __forceinline__ void split_store4(__nv_bfloat16* hi, __nv_bfloat16* lo, float4 v) {
    __nv_bfloat16 h0 = __float2bfloat16(v.x);
    __nv_bfloat16 h1 = __float2bfloat16(v.y);
    __nv_bfloat16 h2 = __float2bfloat16(v.z);
    __nv_bfloat16 h3 = __float2bfloat16(v.w);
    __nv_bfloat16 l0 = __float2bfloat16(v.x - __bfloat162float(h0));
    __nv_bfloat16 l1 = __float2bfloat16(v.y - __bfloat162float(h1));
    __nv_bfloat16 l2 = __float2bfloat16(v.z - __bfloat162float(h2));
    __nv_bfloat16 l3 = __float2bfloat16(v.w - __bfloat162float(h3));
    __nv_bfloat162* hp = reinterpret_cast<__nv_bfloat162*>(hi);
    __nv_bfloat162* lp = reinterpret_cast<__nv_bfloat162*>(lo);
    hp[0] = __halves2bfloat162(h0, h1);
    hp[1] = __halves2bfloat162(h2, h3);
    lp[0] = __halves2bfloat162(l0, l1);
    lp[1] = __halves2bfloat162(l2, l3);
}

__global__ __launch_bounds__(256) void conv_a_kernel(const float* __restrict__ x,
                                                     const float* __restrict__ h) {
    const size_t e = ((size_t)blockIdx.x * 256 + threadIdx.x) * 4;
    if (e >= (size_t)BATCH_ * 2048) return;
    const int row = (int)(e >> 11);
    const int col = (int)(e & 2047);
    const float4 xv = *reinterpret_cast<const float4*>(x + e);
    const float4 hv = *reinterpret_cast<const float4*>(h + e);
    const size_t base = (size_t)row * KTOT + col;
    split_store4(g_A_hi + base, g_A_lo + base, xv);
    split_store4(g_A_hi + base + 2048, g_A_lo + base + 2048, hv);
}

__global__ __launch_bounds__(256) void conv_w_kernel(const float* __restrict__ w_ih,
                                                     const float* __restrict__ w_hh) {
    __shared__ float t[32][33];
    const int g = blockIdx.z;
    const int kt = blockIdx.y * 32;
    const int nt = blockIdx.x * 32;
    const int tx = threadIdx.x;   // 32
    const int ty = threadIdx.y;   // 8
#pragma unroll
    for (int r = 0; r < 4; r++) {
        const int kk = kt + ty + r * 8;
        const float* src = (kk < 2048)
            ? (w_ih + ((size_t)g * 2048 + kk) * HID_)
            : (w_hh + ((size_t)g * 2048 + (kk - 2048)) * HID_);
        t[ty + r * 8][tx] = src[nt + tx];
    }
    __syncthreads();
#pragma unroll
    for (int r = 0; r < 4; r++) {
        const int nn = nt + ty + r * 8;
        const float v = t[tx][ty + r * 8];
        const __nv_bfloat16 hi = __float2bfloat16(v);
        const __nv_bfloat16 lo = __float2bfloat16(v - __bfloat162float(hi));
        const size_t off = ((size_t)g * HID_ + nn) * KTOT + kt + tx;
        g_B_hi[off] = hi;
        g_B_lo[off] = lo;
    }
}

// ---------------- fused bf16 3-split GEMM + LSTM epilogue ----------------
__device__ __forceinline__ float sigmoid_f(float v) { return 1.0f / (1.0f + expf(-v)); }

__global__ __launch_bounds__(256, 1) void lstm_fused_kernel(
    const float* __restrict__ cprev, const float* __restrict__ b_ih,
    const float* __restrict__ b_hh, float* __restrict__ out)
{
    extern __shared__ char smem[];
    const uint32_t sb = smem_u32(smem);
    const int tid = threadIdx.x;
    const int wid = tid >> 5;
    const int lid = tid & 31;
    const int wr = wid >> 2;       // 0..1  (64-row m band)
    const int wc = wid & 3;        // 0..3  == GATE index (64-col band of the 256 B rows)
    const int m0 = blockIdx.x * BM;
    const int n0 = blockIdx.y * BN;

    // ---- producer per-thread constants ----
    // A: 128 rows x 32k hi+lo (512 x 16B each); j in 0..1
    size_t gA[2]; uint32_t oA[2];
    // B: 256 rows x 32k hi+lo (1024 x 16B each); j in 0..3; row r: gate=r>>6, n=n0+(r&63)
    size_t gB[4]; uint32_t oB[4];
#pragma unroll
    for (int j = 0; j < 2; j++) {
        const int idx = tid + j * 256;
        const int r = idx >> 2, k2 = idx & 3;
        oA[j] = sw64(r, k2);
        gA[j] = (size_t)(m0 + r) * KTOT + k2 * 8;
    }
#pragma unroll
    for (int j = 0; j < 4; j++) {
        const int idx = tid + j * 256;
        const int r = idx >> 2, k2 = idx & 3;
        oB[j] = sw64(r, k2);
        gB[j] = ((size_t)(r >> 6) * HID_ + n0 + (r & 63)) * KTOT + k2 * 8;
    }

    // ---- consumer per-thread ldmatrix offsets (ko=0; ko=1 == ^32) ----
    const int lrow = lid & 15;
    const int lk2  = lid >> 4;
    uint32_t aOff[4], bOff[4];
#pragma unroll
    for (int i = 0; i < 4; i++)  aOff[i] = sw64(wr * 64 + i * 16 + lrow, lk2);
#pragma unroll
    for (int nt = 0; nt < 4; nt++) bOff[nt] = sw64(wc * 64 + nt * 16 + lrow, lk2);

    float acc[4][8][4];
#pragma unroll
    for (int i = 0; i < 4; i++)
#pragma unroll
        for (int j = 0; j < 8; j++)
#pragma unroll
            for (int p = 0; p < 4; p++) acc[i][j][p] = 0.0f;

    auto load_stage = [&](int kt) {
        const uint32_t base = sb + (uint32_t)(kt & (STAGES - 1)) * ST_BYTES;
        const int k0 = kt * BK;
#pragma unroll
        for (int j = 0; j < 2; j++) {
            cp16(base + OFF_AHI + oA[j], g_A_hi + gA[j] + k0);
            cp16(base + OFF_ALO + oA[j], g_A_lo + gA[j] + k0);
        }
#pragma unroll
        for (int j = 0; j < 4; j++) {
            cp16(base + OFF_BHI + oB[j], g_B_hi + gB[j] + k0);
            cp16(base + OFF_BLO + oB[j], g_B_lo + gB[j] + k0);
        }
    };

#pragma unroll
    for (int kt = 0; kt < STAGES - 1; kt++) { load_stage(kt); cp_commit(); }

    for (int kt = 0; kt < NKC; kt++) {
        cp_wait<STAGES - 2>();
        __syncthreads();           // stage kt ready; WAR-guards refill of stage (kt+3)&3

        // issue next stage's loads FIRST so DMA overlaps the whole MMA burst
        const int np = kt + STAGES - 1;
        if (np < NKC) load_stage(np);
        cp_commit();

        const uint32_t base = sb + (uint32_t)(kt & (STAGES - 1)) * ST_BYTES;

#pragma unroll
        for (int ko = 0; ko < 2; ko++) {           // two k16 steps per k32 stage
            const uint32_t x32 = ko ? 32u : 0u;
            uint32_t ah[4][4], al[4][4], bh[4][4], bl[4][4];
#pragma unroll
            for (int i = 0; i < 4; i++) {
                ldsm4(ah[i], base + OFF_AHI + (aOff[i] ^ x32));
                ldsm4(al[i], base + OFF_ALO + (aOff[i] ^ x32));
            }
#pragma unroll
            for (int nt = 0; nt < 4; nt++) {
                ldsm4(bh[nt], base + OFF_BHI + (bOff[nt] ^ x32));
                ldsm4(bl[nt], base + OFF_BLO + (bOff[nt] ^ x32));
            }
            // pass 1: hi*hi  (32 independent MMAs)
#pragma unroll
            for (int nt = 0; nt < 4; nt++)
#pragma unroll
                for (int i = 0; i < 4; i++) {
                    mma16816(acc[i][2 * nt],     ah[i], bh[nt][0], bh[nt][2]);
                    mma16816(acc[i][2 * nt + 1], ah[i], bh[nt][1], bh[nt][3]);
                }
            // pass 2: lo*hi
#pragma unroll
            for (int nt = 0; nt < 4; nt++)
#pragma unroll
                for (int i = 0; i < 4; i++) {
                    mma16816(acc[i][2 * nt],     al[i], bh[nt][0], bh[nt][2]);
                    mma16816(acc[i][2 * nt + 1], al[i], bh[nt][1], bh[nt][3]);
                }
            // pass 3: hi*lo
#pragma unroll
            for (int nt = 0; nt < 4; nt++)
#pragma unroll
                for (int i = 0; i < 4; i++) {
                    mma16816(acc[i][2 * nt],     ah[i], bl[nt][0], bl[nt][2]);
                    mma16816(acc[i][2 * nt + 1], ah[i], bl[nt][1], bl[nt][3]);
                }
        }
    }

    // ---------------- fused epilogue: exchange via smem, then pointwise ----------------
    cp_wait<0>();
    __syncthreads();
    float* eps = reinterpret_cast<float*>(smem);

    // store accumulators: eps[row][gate*64 + col]
#pragma unroll
    for (int i = 0; i < 4; i++) {
        const int r0 = wr * 64 + i * 16 + (lid >> 2);
        const int r1 = r0 + 8;
#pragma unroll
        for (int n8 = 0; n8 < 8; n8++) {
            const int coloff = wc * 64 + n8 * 8 + (lid & 3) * 2;
            eps[r0 * EPS_STRIDE + coloff]     = acc[i][n8][0];
            eps[r0 * EPS_STRIDE + coloff + 1] = acc[i][n8][1];
            eps[r1 * EPS_STRIDE + coloff]     = acc[i][n8][2];
            eps[r1 * EPS_STRIDE + coloff + 1] = acc[i][n8][3];
        }
    }
    // bias sums: 4 gates x 64 cols
    {
        const int g = tid >> 6, cc = tid & 63;
        eps[BIAS_OFF + tid] = b_ih[g * HID_ + n0 + cc] + b_hh[g * HID_ + n0 + cc];
    }
    __syncthreads();

    // 8 passes: 16 rows x (16 lanes * 4 cols = 64 cols); coalesced 256B global writes
#pragma unroll 1
    for (int p = 0; p < 8; p++) {
        const int row = (tid >> 4) + p * 16;
        const int ct  = (tid & 15) * 4;
        const float* er = eps + row * EPS_STRIDE;
        const size_t gbase = (size_t)(m0 + row) * HID_ + n0 + ct;
        const float4 cv = *reinterpret_cast<const float4*>(cprev + gbase);
        float4 hn, cn;
#pragma unroll
        for (int j = 0; j < 4; j++) {
            const int cc = ct + j;
            const float gi = er[cc]        + eps[BIAS_OFF + cc];
            const float gf = er[64 + cc]   + eps[BIAS_OFF + 64 + cc];
            const float gc = er[128 + cc]  + eps[BIAS_OFF + 128 + cc];
            const float go = er[192 + cc]  + eps[BIAS_OFF + 192 + cc];
            const float ig = sigmoid_f(gi);
            const float fg = sigmoid_f(gf);
            const float cg = tanhf(gc);
            const float og = sigmoid_f(go);
            const float cpv = (j == 0) ? cv.x : (j == 1) ? cv.y : (j == 2) ? cv.z : cv.w;
            const float cnv = fg * cpv + ig * cg;
            const float hnv = og * tanhf(cnv);
            if (j == 0) { hn.x = hnv; cn.x = cnv; }
            else if (j == 1) { hn.y = hnv; cn.y = cnv; }
            else if (j == 2) { hn.z = hnv; cn.z = cnv; }
            else { hn.w = hnv; cn.w = cnv; }
        }
        *reinterpret_cast<float4*>(out + gbase)      = hn;
        *reinterpret_cast<float4*>(out + BH + gbase) = cn;
    }
}

// ---------------- launch ----------------
extern "C" void kernel_launch(void* const* d_in, const int* in_sizes, int n_in,
                              void* d_out, int out_size)
{
    (void)in_sizes; (void)n_in; (void)out_size;
    const float* x    = (const float*)d_in[0];
    const float* h    = (const float*)d_in[1];
    const float* c    = (const float*)d_in[2];
    const float* w_ih = (const float*)d_in[3];
    const float* w_hh = (const float*)d_in[4];
    const float* b_ih = (const float*)d_in[5];
    const float* b_hh = (const float*)d_in[6];
    float* out = (float*)d_out;

    // 1) split x|h into bf16 hi/lo A [4096, 4096]
    conv_a_kernel<<<(BATCH_ * 2048 / 4 + 255) / 256, 256>>>(x, h);

    // 2) transpose + split weights -> Bt [8192, 4096] hi/lo
    dim3 gw(HID_ / 32, KTOT / 32, 4);
    conv_w_kernel<<<gw, dim3(32, 8)>>>(w_ih, w_hh);

    // 3) fused tensor-core GEMM + LSTM epilogue (m-fastest grid for B-panel L2 reuse)
    cudaFuncSetAttribute(lstm_fused_kernel,
                         cudaFuncAttributeMaxDynamicSharedMemorySize, SMEM_TOTAL);
    dim3 gg(BATCH_ / BM, HID_ / BN);   // (32, 32)
    lstm_fused_kernel<<<gg, 256, SMEM_TOTAL>>>(c, b_ih, b_hh, out);
}